// round 1
// baseline (speedup 1.0000x reference)
#include <cuda_runtime.h>
#include <cuda_bf16.h>
#include <math.h>

// Problem constants
#define NB 16               // batch
#define FH 192
#define FW 192
#define NA 9                // anchors per cell
#define N_ANCH (FH*FW*NA)   // 331776
#define PRE 6000            // pre-NMS top-k
#define POST 1000           // post-NMS boxes
#define CAND_CAP 8192
#define NBINS 65536
#define IOU_THR 0.7f

// ---------------- static scratch (no allocations allowed) ----------------
__device__ unsigned g_hist[NB * NBINS];          // 4 MB
__device__ unsigned g_cnt[NB];
__device__ unsigned g_tbin[NB];
__device__ unsigned long long g_cand[NB * CAND_CAP]; // 1 MB
__device__ float4 g_boxes[NB * PRE];
__device__ float  g_area[NB * PRE];

// ---------------- K0: zero counters + histogram ----------------
__global__ void k_zero() {
    int i = blockIdx.x * blockDim.x + threadIdx.x;
    if (i < NB * NBINS) g_hist[i] = 0;
    if (i < NB) g_cnt[i] = 0;
}

// ---------------- K1: per-image histogram of score bits ----------------
// grid (N_ANCH/256, NB) x 256
__global__ void k_hist(const float* __restrict__ labels) {
    int n = blockIdx.x * blockDim.x + threadIdx.x;
    int img = blockIdx.y;
    unsigned key = __float_as_uint(labels[(size_t)img * N_ANCH + n]);
    unsigned bin = min(key >> 14, (unsigned)(NBINS - 1));
    atomicAdd(&g_hist[img * NBINS + bin], 1u);
}

// ---------------- K2: find threshold bin so that count(bin >= T) >= PRE ----------------
__global__ void k_thresh() {
    int img = blockIdx.x, tid = threadIdx.x;
    __shared__ unsigned sc[1024];
    __shared__ int found;
    __shared__ unsigned runBase;
    if (tid == 0) { found = 0; runBase = 0; }
    __syncthreads();
    for (int cs = NBINS - 1024; cs >= 0; cs -= 1024) {
        sc[tid] = g_hist[img * NBINS + cs + tid];
        __syncthreads();
        if (tid == 0) {
            unsigned run = runBase;
            for (int t = 1023; t >= 0; t--) {
                unsigned c = sc[t];
                if (run + c >= PRE) { g_tbin[img] = (unsigned)(cs + t); found = 1; break; }
                run += c;
            }
            runBase = run;
        }
        __syncthreads();
        if (found) return;
    }
    if (tid == 0) g_tbin[img] = 0;
}

// ---------------- K3: compact candidates (bin >= T) with sortable 64-bit key ----------------
// key = (~score_bits)<<32 | index  -> ascending sort == (score desc, index asc)
__global__ void k_compact(const float* __restrict__ labels) {
    int n = blockIdx.x * blockDim.x + threadIdx.x;
    int img = blockIdx.y;
    unsigned key = __float_as_uint(labels[(size_t)img * N_ANCH + n]);
    unsigned bin = min(key >> 14, (unsigned)(NBINS - 1));
    if (bin >= g_tbin[img]) {
        unsigned pos = atomicAdd(&g_cnt[img], 1u);
        if (pos < CAND_CAP)
            g_cand[img * CAND_CAP + pos] =
                ((unsigned long long)(~key) << 32) | (unsigned)n;
    }
}

// ---------------- K4: per-image bitonic sort of 8192 keys in shared ----------------
__global__ void k_sort() {
    extern __shared__ unsigned long long s[];
    int img = blockIdx.x, tid = threadIdx.x;
    unsigned M = min(g_cnt[img], (unsigned)CAND_CAP);
    for (int j = tid; j < CAND_CAP; j += 1024)
        s[j] = (j < (int)M) ? g_cand[img * CAND_CAP + j] : 0xFFFFFFFFFFFFFFFFull;
    __syncthreads();
    for (int k = 2; k <= CAND_CAP; k <<= 1) {
        for (int j = k >> 1; j > 0; j >>= 1) {
            for (int i = tid; i < CAND_CAP; i += 1024) {
                int ixj = i ^ j;
                if (ixj > i) {
                    bool up = ((i & k) == 0);
                    unsigned long long a = s[i], b = s[ixj];
                    if ((a > b) == up) { s[i] = b; s[ixj] = a; }
                }
            }
            __syncthreads();
        }
    }
    // write back only the part we need (top PRE)
    for (int j = tid; j < PRE; j += 1024)
        g_cand[img * CAND_CAP + j] = s[j];
}

// ---------------- K5: decode top-PRE boxes (anchor on the fly), clip, area ----------------
// grid ((PRE+255)/256, NB)
__global__ void k_decode(const float* __restrict__ deltas,
                         const float* __restrict__ base) {
    int p = blockIdx.x * blockDim.x + threadIdx.x;
    int img = blockIdx.y;
    if (p >= PRE) return;
    unsigned long long key = g_cand[img * CAND_CAP + p];
    unsigned idx = (unsigned)key;
    int a = idx % NA;
    int cell = idx / NA;
    int row = cell / FW;
    int col = cell % FW;
    float cy = ((float)row + 0.5f) / (float)FH;
    float cx = ((float)col + 0.5f) / (float)FW;
    float b0 = base[a * 4 + 0], b1 = base[a * 4 + 1];
    float b2 = base[a * 4 + 2], b3 = base[a * 4 + 3];
    float ay1 = fminf(fmaxf(cy + b0, 0.f), 1.f);
    float ax1 = fminf(fmaxf(cx + b1, 0.f), 1.f);
    float ay2 = fminf(fmaxf(cy + b2, 0.f), 1.f);
    float ax2 = fminf(fmaxf(cx + b3, 0.f), 1.f);
    float ah = ay2 - ay1, aw = ax2 - ax1;
    float acy = ay1 + 0.5f * ah, acx = ax1 + 0.5f * aw;
    const float4 d = *(const float4*)(deltas +
        ((size_t)((size_t)img * FH + row) * FW + col) * (NA * 4) + a * 4);
    float h = expf(d.z * 0.2f) * ah;
    float w = expf(d.w * 0.2f) * aw;
    float ccy = d.x * 0.1f * ah + acy;
    float ccx = d.y * 0.1f * aw + acx;
    float y1 = fminf(fmaxf(ccy - 0.5f * h, 0.f), 1.f);
    float x1 = fminf(fmaxf(ccx - 0.5f * w, 0.f), 1.f);
    float y2 = fminf(fmaxf(ccy + 0.5f * h, 0.f), 1.f);
    float x2 = fminf(fmaxf(ccx + 0.5f * w, 0.f), 1.f);
    g_boxes[img * PRE + p] = make_float4(y1, x1, y2, x2);
    g_area[img * PRE + p] = fmaxf(y2 - y1, 0.f) * fmaxf(x2 - x1, 0.f);
}

// ---------------- K6: sequential greedy NMS, one block per image ----------------
// Dynamic shared: boxes (96000 B) | areas (24000 B) | suppressed bytes (6000 B)
#define SM_BOXES 0
#define SM_AREA  96000
#define SM_SUP   120000
#define SM_TOTAL 126080

__global__ void k_nms(float* __restrict__ out) {
    extern __shared__ char sm[];
    float4* sb = (float4*)(sm + SM_BOXES);
    float* sa = (float*)(sm + SM_AREA);
    unsigned char* sup = (unsigned char*)(sm + SM_SUP);
    __shared__ int s_sel, s_emit, s_done, s_cur;

    int img = blockIdx.x, tid = threadIdx.x, nt = blockDim.x;
    for (int j = tid; j < PRE; j += nt) {
        sb[j] = g_boxes[img * PRE + j];
        sa[j] = g_area[img * PRE + j];
        sup[j] = 0;
    }
    if (tid == 0) { s_emit = 0; s_done = 0; s_cur = 0; }
    __syncthreads();

    while (true) {
        if (tid == 0) {
            int i = s_cur;
            while (i < PRE && sup[i]) i++;
            if (i >= PRE || s_emit >= POST) {
                s_done = 1;
            } else {
                s_sel = i;
                s_cur = i + 1;
                float4 b = sb[i];
                float* o = out + ((size_t)img * POST + s_emit) * 4;
                o[0] = b.x; o[1] = b.y; o[2] = b.z; o[3] = b.w;
                s_emit++;
            }
        }
        __syncthreads();
        if (s_done) break;
        int sel = s_sel;
        float4 b = sb[sel];
        float basea = sa[sel] + 1e-8f;
        for (int j = sel + 1 + tid; j < PRE; j += nt) {
            if (sup[j]) continue;
            float4 c = sb[j];
            float y1 = fmaxf(b.x, c.x), x1 = fmaxf(b.y, c.y);
            float y2 = fminf(b.z, c.z), x2 = fminf(b.w, c.w);
            float ih = fmaxf(y2 - y1, 0.f), iw = fmaxf(x2 - x1, 0.f);
            float inter = ih * iw;
            // iou > thr  <=>  inter > thr * (area_i + area_j - inter + 1e-8)
            if (inter > IOU_THR * (basea + sa[j] - inter)) sup[j] = 1;
        }
        __syncthreads();
    }
    // zero-pad remaining rows (d_out is poisoned, must write everything)
    int emit = s_emit;
    for (int r = emit + tid; r < POST; r += nt) {
        float4 z = make_float4(0.f, 0.f, 0.f, 0.f);
        ((float4*)out)[(size_t)img * POST + r] = z;
    }
}

// ---------------- launch ----------------
extern "C" void kernel_launch(void* const* d_in, const int* in_sizes, int n_in,
                              void* d_out, int out_size) {
    const float* deltas = (const float*)d_in[0];   // (16,192,192,36)
    const float* labels = (const float*)d_in[1];   // (16,192,192,9)
    const float* base   = (const float*)d_in[2];   // (9,4)
    float* out = (float*)d_out;                    // (16,1000,4)

    // idempotent, non-stream API calls (safe during capture)
    cudaFuncSetAttribute(k_sort, cudaFuncAttributeMaxDynamicSharedMemorySize, CAND_CAP * 8);
    cudaFuncSetAttribute(k_nms, cudaFuncAttributeMaxDynamicSharedMemorySize, SM_TOTAL);

    k_zero<<<(NB * NBINS + 255) / 256, 256>>>();
    dim3 gfull(N_ANCH / 256, NB);
    k_hist<<<gfull, 256>>>(labels);
    k_thresh<<<NB, 1024>>>();
    k_compact<<<gfull, 256>>>(labels);
    k_sort<<<NB, 1024, CAND_CAP * 8>>>();
    dim3 gdec((PRE + 255) / 256, NB);
    k_decode<<<gdec, 256>>>(deltas, base);
    k_nms<<<NB, 1024, SM_TOTAL>>>(out);
}